// round 13
// baseline (speedup 1.0000x reference)
#include <cuda_runtime.h>
#include <cuda_bf16.h>
#include <math.h>
#include <float.h>
#include <stdint.h>

#define BSZ 256
#define DIM 1024
#define SS  32768

#define GBM 128
#define GBN 64
#define BK  64
#define NIT (DIM / BK)      // 16
#define NT  (SS / GBN)      // 512 n-tiles

#define LDWA 36             // smem pitch in words: 32 data (64 bf16) + 4 pad
#define ASTG_W (GBM * LDWA) // 4608 words / stage
#define BB_W   (GBN * LDWA) // 2304 words / stage
#define A_OFF  0
#define BB_OFF (3 * ASTG_W * 4)          // 55296
#define DSMEM  (BB_OFF + 2 * BB_W * 4)   // 73728 B

// -------- device scratch (allocation-free rule) --------
__device__ __align__(16) __nv_bfloat16 g_xbf[(size_t)BSZ * DIM];   // 0.5 MB, L2-resident
__device__ float g_pz [(size_t)BSZ * NT];
__device__ float g_ptl[(size_t)BSZ * NT];
__device__ float g_pst[(size_t)BSZ * NT];
__device__ float g_row[BSZ];
__device__ int   g_cnt;

// ---------------------------------------------------------------------------
__global__ void convert_x_kernel(const float* __restrict__ x)
{
    if (blockIdx.x == 0 && threadIdx.x == 0) g_cnt = 0;
    int i = blockIdx.x * blockDim.x + threadIdx.x;
    float4 v = ((const float4*)x)[i];
    __nv_bfloat162 p0 = __floats2bfloat162_rn(v.x, v.y);
    __nv_bfloat162 p1 = __floats2bfloat162_rn(v.z, v.w);
    uint2 o;
    o.x = *(const unsigned int*)&p0;
    o.y = *(const unsigned int*)&p1;
    ((uint2*)g_xbf)[i] = o;
}

__device__ __forceinline__ void mma16816(float* d, const uint32_t* a, const uint32_t* b)
{
    asm volatile(
        "mma.sync.aligned.m16n8k16.row.col.f32.bf16.bf16.f32 "
        "{%0,%1,%2,%3},{%4,%5,%6,%7},{%8,%9},{%0,%1,%2,%3};"
        : "+f"(d[0]), "+f"(d[1]), "+f"(d[2]), "+f"(d[3])
        : "r"(a[0]), "r"(a[1]), "r"(a[2]), "r"(a[3]), "r"(b[0]), "r"(b[1]));
}
__device__ __forceinline__ uint32_t smem_u32(const void* p) {
    uint32_t a;
    asm("{ .reg .u64 t; cvta.to.shared.u64 t, %1; cvt.u32.u64 %0, t; }" : "=r"(a) : "l"(p));
    return a;
}
#define CP16(dst, src) \
    asm volatile("cp.async.cg.shared.global [%0], [%1], 16;" :: "r"(dst), "l"(src))
#define CP_COMMIT() asm volatile("cp.async.commit_group;" ::: "memory")
#define CP_WAIT(n)  asm volatile("cp.async.wait_group %0;" :: "n"(n) : "memory")

// ---------------------------------------------------------------------------
// Fused: A bf16 via 3-stage cp.async; gathered fp32 B rows via LDG->regs->
// bf16 STS (pipelined one stage ahead, converted in the HMMA shadow);
// bf16 HMMA GEMM; bias + masked-softmax loss partials.
// grid (2, 512), 256 thr (8 warps, 2m x 4n), warp tile 64x16, BK=64.
// One __syncthreads per mainloop iteration.
// ---------------------------------------------------------------------------
__global__ __launch_bounds__(256, 2) void fused_gemm_kernel(
    const float* __restrict__ weight, const float* __restrict__ bias,
    const int* __restrict__ sid,
    const float* __restrict__ targets, const int* __restrict__ san)
{
    extern __shared__ char dyn[];
    uint32_t* sAp = (uint32_t*)(dyn + A_OFF);    // [3][128][36]
    uint32_t* sBp = (uint32_t*)(dyn + BB_OFF);   // [2][64][36]
    __shared__ float sbias[GBN];
    __shared__ int   srid[GBN];

    const int tid  = threadIdx.x;
    const int m0   = blockIdx.x * GBM;
    const int n0   = blockIdx.y * GBN;
    const int bn   = blockIdx.y;
    const int wid  = tid >> 5;
    const int lane = tid & 31;
    const int wm   = (wid & 1) * 64;
    const int wn   = (wid >> 1) * 16;
    const int lr   = lane >> 2;
    const int lc   = lane & 3;

    if (tid < GBN) {
        int r = __ldg(&sid[n0 + tid]);
        srid[tid] = r;
        sbias[tid] = bias[r];
    }
    __syncthreads();

    // A cp.async roles: 2 threads per row, 64 B each
    const int arow = tid >> 1;
    const int ah   = tid & 1;
    const char* gA = (const char*)(g_xbf + (size_t)(m0 + arow) * DIM);
    const uint32_t base = smem_u32(dyn);
    const uint32_t dA = base + A_OFF + (arow * LDWA + ah * 16) * 4;

    // B LDG roles: 4 threads per row, 16 floats each
    const int brow = tid >> 2;
    const int bq   = tid & 3;
    const float4* gB = (const float4*)(weight + (size_t)srid[brow] * DIM) + bq * 4;

    float acc[4][2][4];
#pragma unroll
    for (int i = 0; i < 4; i++)
#pragma unroll
        for (int j = 0; j < 2; j++)
#pragma unroll
            for (int c = 0; c < 4; c++) acc[i][j][c] = 0.f;

    // prologue: A stages 0,1 in flight; B stage 0 -> regs -> bb0
#pragma unroll
    for (int s = 0; s < 2; s++) {
#pragma unroll
        for (int j = 0; j < 4; j++)
            CP16(dA + s * (ASTG_W * 4) + j * 16, gA + s * 128 + ah * 64 + j * 16);
        CP_COMMIT();
    }
    {
        float4 c0 = gB[0], c1 = gB[1], c2 = gB[2], c3 = gB[3];
        uint4 o0, o1;
        __nv_bfloat162 t;
        t = __floats2bfloat162_rn(c0.x, c0.y); o0.x = *(unsigned*)&t;
        t = __floats2bfloat162_rn(c0.z, c0.w); o0.y = *(unsigned*)&t;
        t = __floats2bfloat162_rn(c1.x, c1.y); o0.z = *(unsigned*)&t;
        t = __floats2bfloat162_rn(c1.z, c1.w); o0.w = *(unsigned*)&t;
        t = __floats2bfloat162_rn(c2.x, c2.y); o1.x = *(unsigned*)&t;
        t = __floats2bfloat162_rn(c2.z, c2.w); o1.y = *(unsigned*)&t;
        t = __floats2bfloat162_rn(c3.x, c3.y); o1.z = *(unsigned*)&t;
        t = __floats2bfloat162_rn(c3.z, c3.w); o1.w = *(unsigned*)&t;
        uint32_t* d = sBp + brow * LDWA + bq * 8;
        *(uint4*)(d + 0) = o0;
        *(uint4*)(d + 4) = o1;
    }

    for (int it = 0; it < NIT; it++) {
        // prefetch A stage it+2
        if (it + 2 < NIT) {
            const int pb = (it + 2) % 3;
#pragma unroll
            for (int j = 0; j < 4; j++)
                CP16(dA + pb * (ASTG_W * 4) + j * 16, gA + (it + 2) * 128 + ah * 64 + j * 16);
            CP_COMMIT();
        }
        CP_WAIT(2);            // A stage it complete (it+1, it+2 may be in flight)
        __syncthreads();       // visibility: A(it) + bb[it&1] STS from last iter

        // issue B LDG for stage it+1 early (hides under MMAs)
        float4 c0, c1, c2, c3;
        const bool more = (it + 1 < NIT);
        if (more) {
            const float4* p = gB + (it + 1) * 16;
            c0 = p[0]; c1 = p[1]; c2 = p[2]; c3 = p[3];
        }

        // ---- MMA on A(it), bb[it&1] ----
        const uint32_t* A = sAp + (it % 3) * ASTG_W;
        const uint32_t* B = sBp + (it & 1) * BB_W;
#pragma unroll
        for (int ks = 0; ks < 4; ks++) {
            const int ktw = ks * 8;
            uint32_t af[4][4], bfr[2][2];
#pragma unroll
            for (int mi = 0; mi < 4; mi++) {
                const int row = wm + mi * 16 + lr;
                af[mi][0] = A[row * LDWA + ktw + lc];
                af[mi][1] = A[(row + 8) * LDWA + ktw + lc];
                af[mi][2] = A[row * LDWA + ktw + 4 + lc];
                af[mi][3] = A[(row + 8) * LDWA + ktw + 4 + lc];
            }
#pragma unroll
            for (int nj = 0; nj < 2; nj++) {
                const int col = wn + nj * 8 + lr;
                bfr[nj][0] = B[col * LDWA + ktw + lc];
                bfr[nj][1] = B[col * LDWA + ktw + 4 + lc];
            }
#pragma unroll
            for (int mi = 0; mi < 4; mi++)
#pragma unroll
                for (int nj = 0; nj < 2; nj++)
                    mma16816(acc[mi][nj], af[mi], bfr[nj]);
        }

        // ---- convert B stage it+1 -> bb[(it+1)&1] in the HMMA shadow ----
        if (more) {
            uint4 o0, o1;
            __nv_bfloat162 t;
            t = __floats2bfloat162_rn(c0.x, c0.y); o0.x = *(unsigned*)&t;
            t = __floats2bfloat162_rn(c0.z, c0.w); o0.y = *(unsigned*)&t;
            t = __floats2bfloat162_rn(c1.x, c1.y); o0.z = *(unsigned*)&t;
            t = __floats2bfloat162_rn(c1.z, c1.w); o0.w = *(unsigned*)&t;
            t = __floats2bfloat162_rn(c2.x, c2.y); o1.x = *(unsigned*)&t;
            t = __floats2bfloat162_rn(c2.z, c2.w); o1.y = *(unsigned*)&t;
            t = __floats2bfloat162_rn(c3.x, c3.y); o1.z = *(unsigned*)&t;
            t = __floats2bfloat162_rn(c3.z, c3.w); o1.w = *(unsigned*)&t;
            uint32_t* d = sBp + ((it + 1) & 1) * BB_W + brow * LDWA + bq * 8;
            *(uint4*)(d + 0) = o0;
            *(uint4*)(d + 4) = o1;
        }
    }

    // ---------------- fused loss epilogue ----------------
    CP_WAIT(0);
    __syncthreads();
    float* sz  = (float*)dyn;
    float* stl = sz + 512;
    float* sst = stl + 512;
    const int g = wid >> 1;

#pragma unroll
    for (int mi = 0; mi < 4; mi++) {
        const int row0 = m0 + wm + mi * 16 + lr;
        const int row1 = row0 + 8;
        const float* tp0 = targets + (size_t)row0 * SS + n0 + wn + 2 * lc;
        const float* tp1 = targets + (size_t)row1 * SS + n0 + wn + 2 * lc;
        const int*   sp0 = san + (size_t)row0 * SS + n0 + wn + 2 * lc;
        const int*   sp1 = san + (size_t)row1 * SS + n0 + wn + 2 * lc;

        float z0 = 0.f, z1 = 0.f, t0 = 0.f, t1 = 0.f, s0 = 0.f, s1 = 0.f;
#pragma unroll
        for (int nj = 0; nj < 2; nj++) {
            const float b0 = sbias[wn + nj * 8 + 2 * lc];
            const float b1 = sbias[wn + nj * 8 + 2 * lc + 1];
            float2 tv0 = *(const float2*)(tp0 + nj * 8);
            float2 tv1 = *(const float2*)(tp1 + nj * 8);
            int2   sv0 = *(const int2*)(sp0 + nj * 8);
            int2   sv1 = *(const int2*)(sp1 + nj * 8);

            float l00 = acc[mi][nj][0] + b0;
            float l01 = acc[mi][nj][1] + b1;
            float l10 = acc[mi][nj][2] + b0;
            float l11 = acc[mi][nj][3] + b1;

            if (sv0.x) z0 += __expf(l00);
            if (sv0.y) z0 += __expf(l01);
            if (sv1.x) z1 += __expf(l10);
            if (sv1.y) z1 += __expf(l11);

            t0 = fmaf(tv0.x, l00, t0); t0 = fmaf(tv0.y, l01, t0);
            t1 = fmaf(tv1.x, l10, t1); t1 = fmaf(tv1.y, l11, t1);
            s0 += tv0.x + tv0.y;
            s1 += tv1.x + tv1.y;
        }
#pragma unroll
        for (int o = 1; o <= 2; o <<= 1) {
            z0 += __shfl_xor_sync(0xffffffffu, z0, o);
            z1 += __shfl_xor_sync(0xffffffffu, z1, o);
            t0 += __shfl_xor_sync(0xffffffffu, t0, o);
            t1 += __shfl_xor_sync(0xffffffffu, t1, o);
            s0 += __shfl_xor_sync(0xffffffffu, s0, o);
            s1 += __shfl_xor_sync(0xffffffffu, s1, o);
        }
        if (lc == 0) {
            const int r0l = wm + mi * 16 + lr;
            sz [g * 128 + r0l]     = z0;
            sz [g * 128 + r0l + 8] = z1;
            stl[g * 128 + r0l]     = t0;
            stl[g * 128 + r0l + 8] = t1;
            sst[g * 128 + r0l]     = s0;
            sst[g * 128 + r0l + 8] = s1;
        }
    }
    __syncthreads();

    if (tid < GBM) {
        const size_t o = (size_t)(m0 + tid) * NT + bn;
        g_pz [o] = sz [tid] + sz [128 + tid] + sz [256 + tid] + sz [384 + tid];
        g_ptl[o] = stl[tid] + stl[128 + tid] + stl[256 + tid] + stl[384 + tid];
        g_pst[o] = sst[tid] + sst[128 + tid] + sst[256 + tid] + sst[384 + tid];
    }
}

// ---------------------------------------------------------------------------
// Loss per row (256 blocks, 512 partials each) + last block computes mean.
// ---------------------------------------------------------------------------
__global__ __launch_bounds__(256) void loss_kernel(float* __restrict__ out)
{
    const int b = blockIdx.x;
    const int tid = threadIdx.x;
    float z  = g_pz [b * NT + tid] + g_pz [b * NT + 256 + tid];
    float tl = g_ptl[b * NT + tid] + g_ptl[b * NT + 256 + tid];
    float st = g_pst[b * NT + tid] + g_pst[b * NT + 256 + tid];
#pragma unroll
    for (int o = 16; o; o >>= 1) {
        z  += __shfl_xor_sync(0xffffffffu, z, o);
        tl += __shfl_xor_sync(0xffffffffu, tl, o);
        st += __shfl_xor_sync(0xffffffffu, st, o);
    }
    __shared__ float rz[8], rtl[8], rst[8];
    __shared__ int slast;
    if ((tid & 31) == 0) { rz[tid >> 5] = z; rtl[tid >> 5] = tl; rst[tid >> 5] = st; }
    __syncthreads();
    if (tid < 32) {
        z  = (tid < 8) ? rz[tid]  : 0.f;
        tl = (tid < 8) ? rtl[tid] : 0.f;
        st = (tid < 8) ? rst[tid] : 0.f;
#pragma unroll
        for (int o = 4; o; o >>= 1) {
            z  += __shfl_xor_sync(0xffffffffu, z, o);
            tl += __shfl_xor_sync(0xffffffffu, tl, o);
            st += __shfl_xor_sync(0xffffffffu, st, o);
        }
        if (tid == 0) {
            g_row[b] = logf(z) * st - tl;
            __threadfence();
            slast = (atomicAdd(&g_cnt, 1) == BSZ - 1);
        }
    }
    __syncthreads();
    if (slast) {
        __shared__ float red[256];
        __threadfence();
        red[tid] = *((volatile float*)&g_row[tid]);
        __syncthreads();
        for (int off = 128; off; off >>= 1) {
            if (tid < off) red[tid] += red[tid + off];
            __syncthreads();
        }
        if (tid == 0) out[0] = red[0] / (float)BSZ;
    }
}

extern "C" void kernel_launch(void* const* d_in, const int* in_sizes, int n_in,
                              void* d_out, int out_size)
{
    const float* x       = (const float*)d_in[0];
    const float* weight  = (const float*)d_in[1];
    const float* bias    = (const float*)d_in[2];
    const float* targets = (const float*)d_in[3];
    const int*   sid     = (const int*)d_in[4];
    const int*   san     = (const int*)d_in[5];

    cudaFuncSetAttribute(fused_gemm_kernel,
                         cudaFuncAttributeMaxDynamicSharedMemorySize, DSMEM);
    convert_x_kernel<<<(BSZ * DIM / 4) / 256, 256>>>(x);
    dim3 gg(BSZ / GBM, SS / GBN);   // (2, 512)
    fused_gemm_kernel<<<gg, 256, DSMEM>>>(weight, bias, sid, targets, san);
    loss_kernel<<<BSZ, 256>>>((float*)d_out);
}